// round 15
// baseline (speedup 1.0000x reference)
#include <cuda_runtime.h>
#include <cuda_bf16.h>
#include <math.h>

// Problem constants
#define BB   16
#define CIN  256
#define COUT 128
#define HH   32
#define WW   32
#define HW   1024          // 32*32
#define KDEF 2304          // 9*256  (deform GEMM K)
#define KUP  512           // 128*4  (deconv GEMM K per parity)
#define N1TOT 16384        // B*HW   (BN1 population)
#define N2TOT 65536        // B*4*HW (BN2 population)

// ---------------- scratch (device globals; no allocation) ----------------
__device__ float g_off_part[4 * 16 * 27 * 1024];          // cin-group partials
__device__ float g_off[16 * 27 * 1024];                   // offsets (raw) + mask (sigmoid)
__device__ float g_wdefT[2304 * 128];                     // deform weights, [kc][o]
__device__ float g_wupT[4 * 512 * 128];                   // deconv sub-kernels, [par][kc][o]
__device__ float g_ypart[3 * 16 * 128 * 1024];            // deform split-K partials (24 MB)
__device__ float g_y[16 * 128 * 1024];                    // deform out (pre-BN)
__device__ float g_z[16 * 4 * 128 * 1024];                // deconv out, parity-blocked (pre-BN)
__device__ float g_part1[2048 * 2];                       // BN1 per-(b,o) partials
__device__ float g_part2[512 * 128 * 2];                  // BN2 per-block partials
__device__ float g_scale1[128], g_shift1[128];
__device__ float g_scale2[128], g_shift2[128];

// ---------------- K1: offset conv 3x3 (256 -> 27), cin split 4 ways ------
__global__ __launch_bounds__(256) void k_offconv(const float* __restrict__ x,
                                                 const float* __restrict__ w_off) {
    const int tile = blockIdx.x;      // 0..3  (8 rows each)
    const int b    = blockIdx.y;      // 0..15
    const int grp  = blockIdx.z;      // 0..3  (64 cin each)
    const int h0   = tile * 8;
    const int c0b  = grp * 64;

    __shared__ float xs[4][10][36];
    __shared__ float ws[4][9][28];

    const int t   = threadIdx.x;
    const int tx  = t & 31;
    const int tyy = t >> 5;

    float acc[27];
#pragma unroll
    for (int i = 0; i < 27; i++) acc[i] = 0.f;

    for (int cc = 0; cc < 64; cc += 4) {
        for (int e = t; e < 4 * 10 * 34; e += 256) {
            int ci = e / 340, rem = e % 340;
            int r = rem / 34, col = rem % 34;
            int gh = h0 - 1 + r, gw = col - 1;
            float v = 0.f;
            if (gh >= 0 && gh < HH && gw >= 0 && gw < WW)
                v = x[(((size_t)b * CIN + c0b + cc + ci) << 10) + gh * WW + gw];
            xs[ci][r][col] = v;
        }
        for (int e = t; e < 4 * 9 * 27; e += 256) {
            int ci = e / 243, rem = e % 243;
            int tap = rem / 27, c27 = rem % 27;
            ws[ci][tap][c27] = w_off[((size_t)c27 * CIN + c0b + cc + ci) * 9 + tap];
        }
        __syncthreads();
#pragma unroll
        for (int ci = 0; ci < 4; ci++) {
#pragma unroll
            for (int tap = 0; tap < 9; tap++) {
                float xv = xs[ci][tyy + tap / 3][tx + tap % 3];
#pragma unroll
                for (int c27 = 0; c27 < 27; c27++)
                    acc[c27] = fmaf(xv, ws[ci][tap][c27], acc[c27]);
            }
        }
        __syncthreads();
    }

    float* op = g_off_part + (size_t)grp * (16 * 27 * 1024) +
                ((size_t)b * 27) * 1024 + (h0 + tyy) * WW + tx;
#pragma unroll
    for (int c27 = 0; c27 < 27; c27++) op[(size_t)c27 << 10] = acc[c27];
}

// K1b: reduce partials + bias; sigmoid on mask channels (18..26)
__global__ void k_offred(const float* __restrict__ b_off) {
    int idx = blockIdx.x * 256 + threadIdx.x;
    if (idx >= 16 * 27 * 1024) return;
    int c27 = (idx >> 10) % 27;
    float v = b_off[c27];
#pragma unroll
    for (int g = 0; g < 4; g++) v += g_off_part[(size_t)g * (16 * 27 * 1024) + idx];
    if (c27 >= 18) v = 1.f / (1.f + expf(-v));
    g_off[idx] = v;
}

// ---------------- weight prepack ----------------
__global__ void k_prep_wdefT(const float* __restrict__ w_dcn) {
    int idx = blockIdx.x * 256 + threadIdx.x;
    if (idx >= 2304 * 128) return;
    int o = idx & 127, kc = idx >> 7;
    int k = kc >> 8, c = kc & 255;
    g_wdefT[idx] = w_dcn[((size_t)o * CIN + c) * 9 + k];
}

__global__ void k_prep_wupT(const float* __restrict__ w_up) {
    int idx = blockIdx.x * 256 + threadIdx.x;
    if (idx >= 4 * 512 * 128) return;
    int o = idx & 127;
    int kcpar = idx >> 7;
    int kc = kcpar & 511, par = kcpar >> 9;
    int i  = kc >> 2, dh = (kc >> 1) & 1, dw = kc & 1;
    int py = par >> 1, px = par & 1;
    int kh = 3 - (py + 2 * dh);
    int kw = 3 - (px + 2 * dw);
    g_wupT[idx] = w_up[(((size_t)i * 128 + o) * 4 + kh) * 4 + kw];
}

// ---------------- K3: FUSED sample+GEMM (M=128, N=128/tile, K=768/grp) ---
// partial[kg][b,o,p] = sum_{kl} wdefT[kg*768+kl][o] * bilinear(x, off, kl, p)
__global__ __launch_bounds__(256) void k_gemm_deform(const float* __restrict__ x) {
    const int pt = blockIdx.x;   // 0..7  (128 spatial cols)
    const int kg = blockIdx.y;   // 0..2  (3 taps each)
    const int b  = blockIdx.z;   // 0..15

    __shared__ float As[8 * 128];
    __shared__ float Bs[8 * 128];
    __shared__ int4   s_idx[3][128];
    __shared__ float4 s_w[3][128];

    const int t  = threadIdx.x;
    const int tx = t & 15, ty = t >> 4;

    // ---- precompute bilinear corners for this block's 3 taps x 128 cols ----
    const float* offb = g_off + (size_t)b * 27 * 1024;
    for (int e = t; e < 3 * 128; e += 256) {
        int tl = e >> 7, p = e & 127;
        int k  = kg * 3 + tl;
        int P  = pt * 128 + p;
        float dy = offb[(size_t)(2 * k) * 1024 + P];
        float dx = offb[(size_t)(2 * k + 1) * 1024 + P];
        float m  = offb[(size_t)(18 + k) * 1024 + P];
        int h = P >> 5, w = P & 31;
        float pyf = (float)(h + (k / 3 - 1)) + dy;
        float pxf = (float)(w + (k % 3 - 1)) + dx;
        float y0f = floorf(pyf), x0f = floorf(pxf);
        float wy = pyf - y0f, wx = pxf - x0f;
        int y0 = (int)y0f, x0 = (int)x0f;
        int   ia[4]; float wa[4];
#pragma unroll
        for (int s = 0; s < 4; s++) {
            int dyc = s >> 1, dxc = s & 1;
            int yc = y0 + dyc, xc = x0 + dxc;
            bool valid = (yc >= 0) && (yc <= HH - 1) && (xc >= 0) && (xc <= WW - 1);
            int yi = min(HH - 1, max(0, yc));
            int xi = min(WW - 1, max(0, xc));
            float wgt = (dyc ? wy : 1.f - wy) * (dxc ? wx : 1.f - wx);
            ia[s] = yi * WW + xi;
            wa[s] = valid ? wgt * m : 0.f;
        }
        s_idx[tl][p] = make_int4(ia[0], ia[1], ia[2], ia[3]);
        s_w[tl][p]   = make_float4(wa[0], wa[1], wa[2], wa[3]);
    }
    __syncthreads();

    float acc[8][8];
#pragma unroll
    for (int i = 0; i < 8; i++)
#pragma unroll
        for (int j = 0; j < 8; j++) acc[i][j] = 0.f;

    const float4* Ag = reinterpret_cast<const float4*>(g_wdefT) + (size_t)kg * 768 * 32;
    const float* xb  = x + ((size_t)b * CIN) * 1024;

    const int r  = t >> 5;           // B-tile row 0..7
    const int n0 = (t & 31) << 2;    // B-tile col base

    for (int kc0 = 0; kc0 < 768; kc0 += 8) {
        reinterpret_cast<float4*>(As)[t] = Ag[kc0 * 32 + t];
        {
            int kl = kc0 + r;
            int c  = kl & 255;
            int tl = kl >> 8;
            const float* xrow = xb + ((size_t)c << 10);
#pragma unroll
            for (int jj = 0; jj < 4; jj++) {
                int p = n0 + jj;
                int4   I = s_idx[tl][p];
                float4 W = s_w[tl][p];
                float v = W.x * __ldg(xrow + I.x) + W.y * __ldg(xrow + I.y) +
                          W.z * __ldg(xrow + I.z) + W.w * __ldg(xrow + I.w);
                Bs[r * 128 + p] = v;
            }
        }
        __syncthreads();
#pragma unroll
        for (int kk = 0; kk < 8; kk++) {
            float a[8], bb[8];
            *(float4*)&a[0]  = *(float4*)&As[kk * 128 + ty * 8];
            *(float4*)&a[4]  = *(float4*)&As[kk * 128 + ty * 8 + 4];
            *(float4*)&bb[0] = *(float4*)&Bs[kk * 128 + tx * 8];
            *(float4*)&bb[4] = *(float4*)&Bs[kk * 128 + tx * 8 + 4];
#pragma unroll
            for (int i = 0; i < 8; i++)
#pragma unroll
                for (int j = 0; j < 8; j++)
                    acc[i][j] = fmaf(a[i], bb[j], acc[i][j]);
        }
        __syncthreads();
    }

    float* Y = g_ypart + (size_t)kg * (16 * 128 * 1024) +
               ((size_t)b * COUT) * 1024 + pt * 128;
#pragma unroll
    for (int i = 0; i < 8; i++) {
        int o = ty * 8 + i;
        *(float4*)(Y + (size_t)o * 1024 + tx * 8)     = *(float4*)&acc[i][0];
        *(float4*)(Y + (size_t)o * 1024 + tx * 8 + 4) = *(float4*)&acc[i][4];
    }
}

// K3b: reduce 3 split-K partials + bias -> y; emit BN1 per-(b,o) sums
__global__ __launch_bounds__(256) void k_red1(const float* __restrict__ bias) {
    const int bo = blockIdx.x;           // 0..2047 = b*128 + o
    const int o  = bo & 127;
    const size_t S4 = (size_t)(16 * 128 * 1024) / 4;
    const size_t base4 = ((size_t)bo << 10) >> 2;
    const int t = threadIdx.x;

    float4 a  = reinterpret_cast<const float4*>(g_ypart)[base4 + t];
    float4 b1 = reinterpret_cast<const float4*>(g_ypart)[S4 + base4 + t];
    float4 c1 = reinterpret_cast<const float4*>(g_ypart)[2 * S4 + base4 + t];
    float bi = __ldg(bias + o);
    float4 v;
    v.x = a.x + b1.x + c1.x + bi;
    v.y = a.y + b1.y + c1.y + bi;
    v.z = a.z + b1.z + c1.z + bi;
    v.w = a.w + b1.w + c1.w + bi;
    reinterpret_cast<float4*>(g_y)[base4 + t] = v;

    float s = v.x + v.y + v.z + v.w;
    float q = v.x * v.x + v.y * v.y + v.z * v.z + v.w * v.w;
#pragma unroll
    for (int m = 16; m > 0; m >>= 1) {
        s += __shfl_xor_sync(0xffffffffu, s, m);
        q += __shfl_xor_sync(0xffffffffu, q, m);
    }
    __shared__ float rs[8], rq[8];
    if ((t & 31) == 0) { rs[t >> 5] = s; rq[t >> 5] = q; }
    __syncthreads();
    if (t == 0) {
        float ss = 0.f, qq = 0.f;
#pragma unroll
        for (int w = 0; w < 8; w++) { ss += rs[w]; qq += rq[w]; }
        g_part1[bo * 2 + 0] = ss;
        g_part1[bo * 2 + 1] = qq;
    }
}

// ---------------- BN1 finalize ----------------
__global__ void k_bn1(const float* __restrict__ g1, const float* __restrict__ bt1) {
    int o = threadIdx.x;  // 128
    float s = 0.f, q = 0.f;
    for (int b = 0; b < 16; b++) {
        s += g_part1[(b * 128 + o) * 2 + 0];
        q += g_part1[(b * 128 + o) * 2 + 1];
    }
    float mean = s / (float)N1TOT;
    float var  = q / (float)N1TOT - mean * mean;
    float sc = g1[o] * rsqrtf(var + 1e-5f);
    g_scale1[o] = sc;
    g_shift1[o] = bt1[o] - mean * sc;
}

// ---------------- K6: deconv as 4 parity 2x2 convs (GEMM), BN1 fused -----
__global__ __launch_bounds__(256) void k_deconv() {
    const int pt  = blockIdx.x;   // 0..7  (4 a-rows x 32 c-cols each)
    const int par = blockIdx.y;   // 0..3
    const int b   = blockIdx.z;   // 0..15
    const int py = par >> 1, px = par & 1;
    const int a0 = pt * 4;
    const int bid = (blockIdx.z * 4 + blockIdx.y) * 8 + blockIdx.x;  // 0..511

    __shared__ float As[8 * 128];
    __shared__ float Bs[8 * 128];
    __shared__ float Red[16 * 128];

    const int t  = threadIdx.x;
    const int tx = t & 15, ty = t >> 4;

    float acc[8][8];
#pragma unroll
    for (int i = 0; i < 8; i++)
#pragma unroll
        for (int j = 0; j < 8; j++) acc[i][j] = 0.f;

    const float4* Ag = reinterpret_cast<const float4*>(g_wupT + (size_t)par * KUP * 128);
    const float* Yb = g_y + (size_t)b * COUT * 1024;

    const int kkld = t >> 5;
    const int n0   = (t & 31) << 2;

    for (int kc0 = 0; kc0 < KUP; kc0 += 8) {
        reinterpret_cast<float4*>(As)[t] = Ag[kc0 * 32 + t];
        {
            int kc = kc0 + kkld;
            int i  = kc >> 2, dh = (kc >> 1) & 1, dw = kc & 1;
            const float* Yp = Yb + (size_t)i * 1024;
            float sc = g_scale1[i], sh = g_shift1[i];
#pragma unroll
            for (int jj = 0; jj < 4; jj++) {
                int n = n0 + jj;
                int arow = n >> 5, c = n & 31;
                int iy = a0 + arow + py + dh - 1;
                int ix = c + px + dw - 1;
                float v = 0.f;
                if (iy >= 0 && iy < HH && ix >= 0 && ix < WW)
                    v = fmaxf(0.f, fmaf(__ldg(Yp + iy * WW + ix), sc, sh));
                Bs[kkld * 128 + n] = v;
            }
        }
        __syncthreads();
#pragma unroll
        for (int kk = 0; kk < 8; kk++) {
            float a[8], bb[8];
            *(float4*)&a[0]  = *(float4*)&As[kk * 128 + ty * 8];
            *(float4*)&a[4]  = *(float4*)&As[kk * 128 + ty * 8 + 4];
            *(float4*)&bb[0] = *(float4*)&Bs[kk * 128 + tx * 8];
            *(float4*)&bb[4] = *(float4*)&Bs[kk * 128 + tx * 8 + 4];
#pragma unroll
            for (int i = 0; i < 8; i++)
#pragma unroll
                for (int j = 0; j < 8; j++)
                    acc[i][j] = fmaf(a[i], bb[j], acc[i][j]);
        }
        __syncthreads();
    }

    float* Z = g_z + ((size_t)(b * 4 + par) * COUT) * 1024 + pt * 128;
    float rs[8], rq[8];
#pragma unroll
    for (int i = 0; i < 8; i++) {
        int o = ty * 8 + i;
        float s = 0.f, q = 0.f;
#pragma unroll
        for (int j = 0; j < 8; j++) { float v = acc[i][j]; s += v; q += v * v; }
        rs[i] = s; rq[i] = q;
        *(float4*)(Z + (size_t)o * 1024 + tx * 8)     = *(float4*)&acc[i][0];
        *(float4*)(Z + (size_t)o * 1024 + tx * 8 + 4) = *(float4*)&acc[i][4];
    }
#pragma unroll
    for (int i = 0; i < 8; i++) Red[tx * 128 + ty * 8 + i] = rs[i];
    __syncthreads();
    if (t < 128) {
        float s = 0.f;
#pragma unroll
        for (int xq = 0; xq < 16; xq++) s += Red[xq * 128 + t];
        g_part2[((size_t)bid * 128 + t) * 2 + 0] = s;
    }
    __syncthreads();
#pragma unroll
    for (int i = 0; i < 8; i++) Red[tx * 128 + ty * 8 + i] = rq[i];
    __syncthreads();
    if (t < 128) {
        float q = 0.f;
#pragma unroll
        for (int xq = 0; xq < 16; xq++) q += Red[xq * 128 + t];
        g_part2[((size_t)bid * 128 + t) * 2 + 1] = q;
    }
}

// ---------------- BN2 finalize + final output (parity de-interleave) ----
__global__ void k_bn2(const float* __restrict__ g2, const float* __restrict__ bt2) {
    int o = threadIdx.x;  // 128
    float s = 0.f, q = 0.f;
    for (int blk = 0; blk < 512; blk++) {
        s += g_part2[((size_t)blk * 128 + o) * 2 + 0];
        q += g_part2[((size_t)blk * 128 + o) * 2 + 1];
    }
    float mean = s / (float)N2TOT;
    float var  = q / (float)N2TOT - mean * mean;
    float sc = g2[o] * rsqrtf(var + 1e-5f);
    g_scale2[o] = sc;
    g_shift2[o] = bt2[o] - mean * sc;
}

__global__ void k_out(float* __restrict__ out) {
    int f = blockIdx.x * 256 + threadIdx.x;  // float4 id, 2097152 total
    int e = f << 2;
    int b   = e >> 19;
    int o   = (e >> 12) & 127;
    int oy  = (e >> 6) & 63;
    int ox0 = e & 63;
    float sc = g_scale2[o], sh = g_shift2[o];
    int a = oy >> 1;
    int pybit = oy & 1;
    float r[4];
#pragma unroll
    for (int j = 0; j < 4; j++) {
        int ox = ox0 + j;
        int par = pybit * 2 + (ox & 1);
        int c = ox >> 1;
        float z = g_z[((size_t)(b * 4 + par) * COUT + o) * 1024 + a * 32 + c];
        r[j] = fmaxf(0.f, z * sc + sh);
    }
    reinterpret_cast<float4*>(out)[f] = *(float4*)r;
}

// ---------------- launcher ----------------
extern "C" void kernel_launch(void* const* d_in, const int* in_sizes, int n_in,
                              void* d_out, int out_size) {
    const float* x     = (const float*)d_in[0];
    const float* w_off = (const float*)d_in[1];
    const float* b_off = (const float*)d_in[2];
    const float* w_dcn = (const float*)d_in[3];
    const float* b_dcn = (const float*)d_in[4];
    const float* g1    = (const float*)d_in[5];
    const float* bt1   = (const float*)d_in[6];
    const float* w_up  = (const float*)d_in[7];
    const float* g2    = (const float*)d_in[8];
    const float* bt2   = (const float*)d_in[9];
    float* out = (float*)d_out;

    // 1) offset conv + reduce (+ sigmoid on mask channels)
    k_offconv<<<dim3(4, 16, 4), 256>>>(x, w_off);
    k_offred<<<1728, 256>>>(b_off);

    // weight prepacks
    k_prep_wdefT<<<1152, 256>>>(w_dcn);
    k_prep_wupT<<<1024, 256>>>(w_up);

    // 2+3) fused bilinear-sample + deform GEMM (split-K over tap triples)
    k_gemm_deform<<<dim3(8, 3, 16), 256>>>(x);
    k_red1<<<2048, 256>>>(b_dcn);
    k_bn1<<<1, 128>>>(g1, bt1);

    // 4) transposed conv (4 parity sub-convs), BN1 normalize fused in B load
    k_deconv<<<dim3(8, 4, 16), 256>>>();
    k_bn2<<<1, 128>>>(g2, bt2);

    // 5) BN2 normalize + parity de-interleave into final NCHW output
    k_out<<<8192, 256>>>(out);
}

// round 16
// speedup vs baseline: 1.3293x; 1.3293x over previous
#include <cuda_runtime.h>
#include <cuda_bf16.h>
#include <math.h>

// Problem constants
#define BB   16
#define CIN  256
#define COUT 128
#define HH   32
#define WW   32
#define HW   1024
#define KDEF 2304          // 9*256  (deform GEMM K)
#define KUP  512           // 128*4  (deconv GEMM K per parity)
#define N1TOT 16384
#define N2TOT 65536

// ---------------- scratch (device globals; no allocation) ----------------
__device__ float g_off_part[4 * 16 * 27 * 1024];
__device__ float g_off[16 * 27 * 1024];
__device__ float g_samp[16 * 9 * 256 * 1024];             // sampled B matrix (151 MB)
__device__ float g_wdefT[2304 * 128];
__device__ float g_wupT[4 * 512 * 128];
__device__ float g_y[16 * 128 * 1024];                    // deform out (pre-BN)
__device__ float g_z[16 * 4 * 128 * 1024];                // deconv out (pre-BN)
__device__ float g_part1[128 * 128 * 2];
__device__ float g_part2[512 * 128 * 2];
__device__ float g_scale1[128], g_shift1[128];
__device__ float g_scale2[128], g_shift2[128];

// ---------------- K1: offset conv 3x3 (256 -> 27) ------------------------
__global__ __launch_bounds__(256) void k_offconv(const float* __restrict__ x,
                                                 const float* __restrict__ w_off) {
    const int tile = blockIdx.x, b = blockIdx.y, grp = blockIdx.z;
    const int h0 = tile * 8;
    const int c0b = grp * 64;

    __shared__ float xs[4][10][36];
    __shared__ float ws[4][9][28];

    const int t = threadIdx.x;
    const int tx = t & 31;
    const int tyy = t >> 5;

    float acc[27];
#pragma unroll
    for (int i = 0; i < 27; i++) acc[i] = 0.f;

    for (int cc = 0; cc < 64; cc += 4) {
        for (int e = t; e < 4 * 10 * 34; e += 256) {
            int ci = e / 340, rem = e % 340;
            int r = rem / 34, col = rem % 34;
            int gh = h0 - 1 + r, gw = col - 1;
            float v = 0.f;
            if (gh >= 0 && gh < HH && gw >= 0 && gw < WW)
                v = x[(((size_t)b * CIN + c0b + cc + ci) << 10) + gh * WW + gw];
            xs[ci][r][col] = v;
        }
        for (int e = t; e < 4 * 9 * 27; e += 256) {
            int ci = e / 243, rem = e % 243;
            int tap = rem / 27, c27 = rem % 27;
            ws[ci][tap][c27] = w_off[((size_t)c27 * CIN + c0b + cc + ci) * 9 + tap];
        }
        __syncthreads();
#pragma unroll
        for (int ci = 0; ci < 4; ci++) {
#pragma unroll
            for (int tap = 0; tap < 9; tap++) {
                float xv = xs[ci][tyy + tap / 3][tx + tap % 3];
#pragma unroll
                for (int c27 = 0; c27 < 27; c27++)
                    acc[c27] = fmaf(xv, ws[ci][tap][c27], acc[c27]);
            }
        }
        __syncthreads();
    }

    float* op = g_off_part + (size_t)grp * (16 * 27 * 1024) +
                ((size_t)b * 27) * 1024 + (h0 + tyy) * WW + tx;
#pragma unroll
    for (int c27 = 0; c27 < 27; c27++) op[(size_t)c27 << 10] = acc[c27];
}

__global__ void k_offred(const float* __restrict__ b_off) {
    int idx = blockIdx.x * 256 + threadIdx.x;
    if (idx >= 16 * 27 * 1024) return;
    int c27 = (idx >> 10) % 27;
    float v = b_off[c27];
#pragma unroll
    for (int g = 0; g < 4; g++) v += g_off_part[(size_t)g * (16 * 27 * 1024) + idx];
    if (c27 >= 18) v = 1.f / (1.f + expf(-v));
    g_off[idx] = v;
}

// ---------------- combined weight prepack ----------------
__global__ void k_prep(const float* __restrict__ w_dcn, const float* __restrict__ w_up) {
    int idx = blockIdx.x * 256 + threadIdx.x;
    if (idx < 2304 * 128) {
        int o = idx & 127, kc = idx >> 7;
        int k = kc >> 8, c = kc & 255;
        g_wdefT[idx] = w_dcn[((size_t)o * CIN + c) * 9 + k];
    } else {
        int j = idx - 2304 * 128;
        if (j < 4 * 512 * 128) {
            int o = j & 127;
            int kcpar = j >> 7;
            int kc = kcpar & 511, par = kcpar >> 9;
            int i = kc >> 2, dh = (kc >> 1) & 1, dw = kc & 1;
            int py = par >> 1, px = par & 1;
            int kh = 3 - (py + 2 * dh);
            int kw = 3 - (px + 2 * dw);
            g_wupT[j] = w_up[(((size_t)i * 128 + o) * 4 + kh) * 4 + kw];
        }
    }
}

// ---------------- K2: bilinear sampling into samp[b][k][c][p] -----------
__global__ __launch_bounds__(256) void k_sample(const float* __restrict__ x) {
    const int k = blockIdx.x;       // 0..8
    const int b = blockIdx.y;       // 0..15
    const int chalf = blockIdx.z;   // 0..1
    const int t = threadIdx.x;

    __shared__ int   s_idx[4][1024];
    __shared__ float s_w[4][1024];

    const float* offb = g_off + (size_t)b * 27 * 1024;
    const int ky = k / 3 - 1, kx = k % 3 - 1;

    for (int p = t; p < 1024; p += 256) {
        float dy = offb[(size_t)(2 * k) * 1024 + p];
        float dx = offb[(size_t)(2 * k + 1) * 1024 + p];
        float m  = offb[(size_t)(18 + k) * 1024 + p];
        int h = p >> 5, w = p & 31;
        float pyf = (float)(h + ky) + dy;
        float pxf = (float)(w + kx) + dx;
        float y0f = floorf(pyf), x0f = floorf(pxf);
        float wy = pyf - y0f, wx = pxf - x0f;
        int y0 = (int)y0f, x0 = (int)x0f;
#pragma unroll
        for (int slot = 0; slot < 4; slot++) {
            int dyc = slot >> 1, dxc = slot & 1;
            int yc = y0 + dyc, xc = x0 + dxc;
            bool valid = (yc >= 0) && (yc <= HH - 1) && (xc >= 0) && (xc <= WW - 1);
            int yi = min(HH - 1, max(0, yc));
            int xi = min(WW - 1, max(0, xc));
            float wgt = (dyc ? wy : 1.f - wy) * (dxc ? wx : 1.f - wx);
            s_idx[slot][p] = yi * WW + xi;
            s_w[slot][p]   = valid ? wgt * m : 0.f;
        }
    }
    __syncthreads();

    const float* xb = x + ((size_t)b * CIN + chalf * 128) * 1024;
    float* Sb = g_samp + (((size_t)(b * 9 + k) * CIN) + chalf * 128) * 1024;

    for (int p = t; p < 1024; p += 256) {
        int   i0 = s_idx[0][p], i1 = s_idx[1][p], i2 = s_idx[2][p], i3 = s_idx[3][p];
        float w0 = s_w[0][p],   w1 = s_w[1][p],   w2 = s_w[2][p],   w3 = s_w[3][p];
        const float* xp = xb;
        float* sp = Sb + p;
#pragma unroll 4
        for (int c = 0; c < 128; c++) {
            float v = w0 * __ldg(xp + i0) + w1 * __ldg(xp + i1) +
                      w2 * __ldg(xp + i2) + w3 * __ldg(xp + i3);
            sp[(size_t)c << 10] = v;
            xp += 1024;
        }
    }
}

// ---------------- K3: deform GEMM, double-buffered  ----------------------
// out[b,o,p] = sum_kc g_wdefT[kc][o] * g_samp[b][kc][p] + bias[o]
__global__ __launch_bounds__(256) void k_gemm_deform(const float* __restrict__ bias) {
    const int pt = blockIdx.x;   // 0..7
    const int b  = blockIdx.y;   // 0..15
    const int bid = blockIdx.y * 8 + blockIdx.x;

    __shared__ float sh[4096];   // 2 x (As 1024 + Bs 1024); Red overlays [0..2047]

    const int t  = threadIdx.x;
    const int tx = t & 15, ty = t >> 4;

    float acc[8][8];
#pragma unroll
    for (int i = 0; i < 8; i++)
#pragma unroll
        for (int j = 0; j < 8; j++) acc[i][j] = 0.f;

    const float* Sb = g_samp + (size_t)b * KDEF * 1024 + pt * 128;
    const float4* Ag = reinterpret_cast<const float4*>(g_wdefT);

    const int r  = t >> 5;
    const int c4 = (t & 31) << 2;

    // prologue: tile 0 -> buf 0
    float4 ra = Ag[t];
    float4 rb = *reinterpret_cast<const float4*>(Sb + (size_t)r * 1024 + c4);
    reinterpret_cast<float4*>(sh)[t] = ra;
    *reinterpret_cast<float4*>(sh + 1024 + r * 128 + c4) = rb;
    __syncthreads();

    int buf = 0;
    for (int kc0 = 0; kc0 < KDEF; kc0 += 8) {
        const int nxt = kc0 + 8;
        if (nxt < KDEF) {
            ra = Ag[nxt * 32 + t];
            rb = *reinterpret_cast<const float4*>(Sb + (size_t)(nxt + r) * 1024 + c4);
        }
        const float* As = sh + buf * 2048;
        const float* Bs = As + 1024;
#pragma unroll
        for (int kk = 0; kk < 8; kk++) {
            float a[8], bb[8];
            *(float4*)&a[0]  = *(const float4*)&As[kk * 128 + ty * 8];
            *(float4*)&a[4]  = *(const float4*)&As[kk * 128 + ty * 8 + 4];
            *(float4*)&bb[0] = *(const float4*)&Bs[kk * 128 + tx * 8];
            *(float4*)&bb[4] = *(const float4*)&Bs[kk * 128 + tx * 8 + 4];
#pragma unroll
            for (int i = 0; i < 8; i++)
#pragma unroll
                for (int j = 0; j < 8; j++)
                    acc[i][j] = fmaf(a[i], bb[j], acc[i][j]);
        }
        if (nxt < KDEF) {
            float* d = sh + (buf ^ 1) * 2048;
            reinterpret_cast<float4*>(d)[t] = ra;
            *reinterpret_cast<float4*>(d + 1024 + r * 128 + c4) = rb;
        }
        __syncthreads();
        buf ^= 1;
    }

    // epilogue: bias, write, BN1 partials (Red overlays sh[0..2047])
    float* Red = sh;
    float* Y = g_y + ((size_t)b * COUT) * 1024 + pt * 128;
    float rs[8], rq[8];
#pragma unroll
    for (int i = 0; i < 8; i++) {
        int o = ty * 8 + i;
        float bi = __ldg(bias + o);
        float s = 0.f, q = 0.f;
#pragma unroll
        for (int j = 0; j < 8; j++) {
            float v = acc[i][j] + bi;
            acc[i][j] = v;
            s += v; q += v * v;
        }
        rs[i] = s; rq[i] = q;
        *(float4*)(Y + (size_t)o * 1024 + tx * 8)     = *(float4*)&acc[i][0];
        *(float4*)(Y + (size_t)o * 1024 + tx * 8 + 4) = *(float4*)&acc[i][4];
    }
#pragma unroll
    for (int i = 0; i < 8; i++) Red[tx * 128 + ty * 8 + i] = rs[i];
    __syncthreads();
    if (t < 128) {
        float s = 0.f;
#pragma unroll
        for (int xq = 0; xq < 16; xq++) s += Red[xq * 128 + t];
        g_part1[((size_t)bid * 128 + t) * 2 + 0] = s;
    }
    __syncthreads();
#pragma unroll
    for (int i = 0; i < 8; i++) Red[tx * 128 + ty * 8 + i] = rq[i];
    __syncthreads();
    if (t < 128) {
        float q = 0.f;
#pragma unroll
        for (int xq = 0; xq < 16; xq++) q += Red[xq * 128 + t];
        g_part1[((size_t)bid * 128 + t) * 2 + 1] = q;
    }
}

// ---------------- BN1 finalize ----------------
__global__ void k_bn1(const float* __restrict__ g1, const float* __restrict__ bt1) {
    int o = threadIdx.x;
    float s = 0.f, q = 0.f;
    for (int blk = 0; blk < 128; blk++) {
        s += g_part1[((size_t)blk * 128 + o) * 2 + 0];
        q += g_part1[((size_t)blk * 128 + o) * 2 + 1];
    }
    float mean = s / (float)N1TOT;
    float var  = q / (float)N1TOT - mean * mean;
    float sc = g1[o] * rsqrtf(var + 1e-5f);
    g_scale1[o] = sc;
    g_shift1[o] = bt1[o] - mean * sc;
}

// ---------------- K6: deconv (4 parity 2x2 convs), BN1 fused, pipelined --
__global__ __launch_bounds__(256) void k_deconv() {
    const int pt  = blockIdx.x;   // 0..7
    const int par = blockIdx.y;   // 0..3
    const int b   = blockIdx.z;   // 0..15
    const int py = par >> 1, px = par & 1;
    const int a0 = pt * 4;
    const int bid = (blockIdx.z * 4 + blockIdx.y) * 8 + blockIdx.x;

    __shared__ float sh[4096];

    const int t  = threadIdx.x;
    const int tx = t & 15, ty = t >> 4;

    float acc[8][8];
#pragma unroll
    for (int i = 0; i < 8; i++)
#pragma unroll
        for (int j = 0; j < 8; j++) acc[i][j] = 0.f;

    const float4* Ag = reinterpret_cast<const float4*>(g_wupT + (size_t)par * KUP * 128);
    const float* Yb = g_y + (size_t)b * COUT * 1024;

    const int kkld = t >> 5;
    const int n0   = (t & 31) << 2;

    // B-tile producer for K-step base kc0 -> 4 register values
    auto loadB = [&](int kc0, float* rv) {
        int kc = kc0 + kkld;
        int i  = kc >> 2, dh = (kc >> 1) & 1, dw = kc & 1;
        const float* Yp = Yb + (size_t)i * 1024;
        float sc = g_scale1[i], shv = g_shift1[i];
#pragma unroll
        for (int jj = 0; jj < 4; jj++) {
            int n = n0 + jj;
            int arow = n >> 5, c = n & 31;
            int iy = a0 + arow + py + dh - 1;
            int ix = c + px + dw - 1;
            float v = 0.f;
            if (iy >= 0 && iy < HH && ix >= 0 && ix < WW)
                v = fmaxf(0.f, fmaf(__ldg(Yp + iy * WW + ix), sc, shv));
            rv[jj] = v;
        }
    };

    // prologue
    float4 ra = Ag[t];
    float rv[4];
    loadB(0, rv);
    reinterpret_cast<float4*>(sh)[t] = ra;
    *reinterpret_cast<float4*>(sh + 1024 + kkld * 128 + n0) = *(float4*)rv;
    __syncthreads();

    int buf = 0;
    for (int kc0 = 0; kc0 < KUP; kc0 += 8) {
        const int nxt = kc0 + 8;
        if (nxt < KUP) {
            ra = Ag[nxt * 32 + t];
            loadB(nxt, rv);
        }
        const float* As = sh + buf * 2048;
        const float* Bs = As + 1024;
#pragma unroll
        for (int kk = 0; kk < 8; kk++) {
            float a[8], bb[8];
            *(float4*)&a[0]  = *(const float4*)&As[kk * 128 + ty * 8];
            *(float4*)&a[4]  = *(const float4*)&As[kk * 128 + ty * 8 + 4];
            *(float4*)&bb[0] = *(const float4*)&Bs[kk * 128 + tx * 8];
            *(float4*)&bb[4] = *(const float4*)&Bs[kk * 128 + tx * 8 + 4];
#pragma unroll
            for (int i = 0; i < 8; i++)
#pragma unroll
                for (int j = 0; j < 8; j++)
                    acc[i][j] = fmaf(a[i], bb[j], acc[i][j]);
        }
        if (nxt < KUP) {
            float* d = sh + (buf ^ 1) * 2048;
            reinterpret_cast<float4*>(d)[t] = ra;
            *reinterpret_cast<float4*>(d + 1024 + kkld * 128 + n0) = *(float4*)rv;
        }
        __syncthreads();
        buf ^= 1;
    }

    float* Red = sh;
    float* Z = g_z + ((size_t)(b * 4 + par) * COUT) * 1024 + pt * 128;
    float rs[8], rq[8];
#pragma unroll
    for (int i = 0; i < 8; i++) {
        int o = ty * 8 + i;
        float s = 0.f, q = 0.f;
#pragma unroll
        for (int j = 0; j < 8; j++) { float v = acc[i][j]; s += v; q += v * v; }
        rs[i] = s; rq[i] = q;
        *(float4*)(Z + (size_t)o * 1024 + tx * 8)     = *(float4*)&acc[i][0];
        *(float4*)(Z + (size_t)o * 1024 + tx * 8 + 4) = *(float4*)&acc[i][4];
    }
#pragma unroll
    for (int i = 0; i < 8; i++) Red[tx * 128 + ty * 8 + i] = rs[i];
    __syncthreads();
    if (t < 128) {
        float s = 0.f;
#pragma unroll
        for (int xq = 0; xq < 16; xq++) s += Red[xq * 128 + t];
        g_part2[((size_t)bid * 128 + t) * 2 + 0] = s;
    }
    __syncthreads();
#pragma unroll
    for (int i = 0; i < 8; i++) Red[tx * 128 + ty * 8 + i] = rq[i];
    __syncthreads();
    if (t < 128) {
        float q = 0.f;
#pragma unroll
        for (int xq = 0; xq < 16; xq++) q += Red[xq * 128 + t];
        g_part2[((size_t)bid * 128 + t) * 2 + 1] = q;
    }
}

// ---------------- BN2 finalize + final output ----------------
__global__ void k_bn2(const float* __restrict__ g2, const float* __restrict__ bt2) {
    int o = threadIdx.x;
    float s = 0.f, q = 0.f;
    for (int blk = 0; blk < 512; blk++) {
        s += g_part2[((size_t)blk * 128 + o) * 2 + 0];
        q += g_part2[((size_t)blk * 128 + o) * 2 + 1];
    }
    float mean = s / (float)N2TOT;
    float var  = q / (float)N2TOT - mean * mean;
    float sc = g2[o] * rsqrtf(var + 1e-5f);
    g_scale2[o] = sc;
    g_shift2[o] = bt2[o] - mean * sc;
}

__global__ void k_out(float* __restrict__ out) {
    int f = blockIdx.x * 256 + threadIdx.x;
    int e = f << 2;
    int b   = e >> 19;
    int o   = (e >> 12) & 127;
    int oy  = (e >> 6) & 63;
    int ox0 = e & 63;
    float sc = g_scale2[o], shv = g_shift2[o];
    int a = oy >> 1;
    int pybit = oy & 1;
    float r[4];
#pragma unroll
    for (int j = 0; j < 4; j++) {
        int ox = ox0 + j;
        int par = pybit * 2 + (ox & 1);
        int c = ox >> 1;
        float z = g_z[((size_t)(b * 4 + par) * COUT + o) * 1024 + a * 32 + c];
        r[j] = fmaxf(0.f, z * sc + shv);
    }
    reinterpret_cast<float4*>(out)[f] = *(float4*)r;
}

// ---------------- launcher ----------------
extern "C" void kernel_launch(void* const* d_in, const int* in_sizes, int n_in,
                              void* d_out, int out_size) {
    const float* x     = (const float*)d_in[0];
    const float* w_off = (const float*)d_in[1];
    const float* b_off = (const float*)d_in[2];
    const float* w_dcn = (const float*)d_in[3];
    const float* b_dcn = (const float*)d_in[4];
    const float* g1    = (const float*)d_in[5];
    const float* bt1   = (const float*)d_in[6];
    const float* w_up  = (const float*)d_in[7];
    const float* g2    = (const float*)d_in[8];
    const float* bt2   = (const float*)d_in[9];
    float* out = (float*)d_out;

    k_offconv<<<dim3(4, 16, 4), 256>>>(x, w_off);
    k_offred<<<1728, 256>>>(b_off);
    k_prep<<<2176, 256>>>(w_dcn, w_up);

    k_sample<<<dim3(9, 16, 2), 256>>>(x);

    k_gemm_deform<<<dim3(8, 16), 256>>>(b_dcn);
    k_bn1<<<1, 128>>>(g1, bt1);

    k_deconv<<<dim3(8, 4, 16), 256>>>();
    k_bn2<<<1, 128>>>(g2, bt2);

    k_out<<<8192, 256>>>(out);
}

// round 17
// speedup vs baseline: 1.3299x; 1.0005x over previous
#include <cuda_runtime.h>
#include <cuda_bf16.h>
#include <math.h>

// Problem constants
#define BB   16
#define CIN  256
#define COUT 128
#define HH   32
#define WW   32
#define HW   1024
#define KDEF 2304          // 9*256  (deform GEMM K)
#define KUP  512           // 128*4  (deconv GEMM K per parity)
#define N1TOT 16384
#define N2TOT 65536

// ---------------- scratch (device globals; no allocation) ----------------
__device__ float g_off_part[4 * 16 * 27 * 1024];
__device__ float g_off[16 * 27 * 1024];
__device__ float g_samp[16 * 9 * 256 * 1024];             // sampled B matrix (151 MB)
__device__ float g_wdefT[2304 * 128];
__device__ float g_wupT[4 * 512 * 128];
__device__ float g_y[16 * 128 * 1024];                    // deform out (pre-BN)
__device__ float g_z[16 * 4 * 128 * 1024];                // deconv out (pre-BN)
__device__ float g_part1[128 * 128 * 2];
__device__ float g_part2[512 * 128 * 2];
__device__ float g_scale1[128], g_shift1[128];
__device__ float g_scale2[128], g_shift2[128];

// ---- packed f32x2 helpers (Blackwell FFMA2 path) ----
__device__ __forceinline__ unsigned long long pack2_dup(float a) {
    unsigned long long r;
    asm("mov.b64 %0, {%1, %1};" : "=l"(r) : "f"(a));
    return r;
}
__device__ __forceinline__ void ffma2(unsigned long long& acc,
                                      unsigned long long a,
                                      unsigned long long b) {
    asm("fma.rn.f32x2 %0, %1, %2, %0;" : "+l"(acc) : "l"(a), "l"(b));
}
__device__ __forceinline__ void unpack2(unsigned long long v, float& lo, float& hi) {
    asm("mov.b64 {%0, %1}, %2;" : "=f"(lo), "=f"(hi) : "l"(v));
}

// ---------------- K1: offset conv 3x3 (256 -> 27) ------------------------
__global__ __launch_bounds__(256) void k_offconv(const float* __restrict__ x,
                                                 const float* __restrict__ w_off) {
    const int tile = blockIdx.x, b = blockIdx.y, grp = blockIdx.z;
    const int h0 = tile * 8;
    const int c0b = grp * 64;

    __shared__ float xs[4][10][36];
    __shared__ float ws[4][9][28];

    const int t = threadIdx.x;
    const int tx = t & 31;
    const int tyy = t >> 5;

    float acc[27];
#pragma unroll
    for (int i = 0; i < 27; i++) acc[i] = 0.f;

    for (int cc = 0; cc < 64; cc += 4) {
        for (int e = t; e < 4 * 10 * 34; e += 256) {
            int ci = e / 340, rem = e % 340;
            int r = rem / 34, col = rem % 34;
            int gh = h0 - 1 + r, gw = col - 1;
            float v = 0.f;
            if (gh >= 0 && gh < HH && gw >= 0 && gw < WW)
                v = x[(((size_t)b * CIN + c0b + cc + ci) << 10) + gh * WW + gw];
            xs[ci][r][col] = v;
        }
        for (int e = t; e < 4 * 9 * 27; e += 256) {
            int ci = e / 243, rem = e % 243;
            int tap = rem / 27, c27 = rem % 27;
            ws[ci][tap][c27] = w_off[((size_t)c27 * CIN + c0b + cc + ci) * 9 + tap];
        }
        __syncthreads();
#pragma unroll
        for (int ci = 0; ci < 4; ci++) {
#pragma unroll
            for (int tap = 0; tap < 9; tap++) {
                float xv = xs[ci][tyy + tap / 3][tx + tap % 3];
#pragma unroll
                for (int c27 = 0; c27 < 27; c27++)
                    acc[c27] = fmaf(xv, ws[ci][tap][c27], acc[c27]);
            }
        }
        __syncthreads();
    }

    float* op = g_off_part + (size_t)grp * (16 * 27 * 1024) +
                ((size_t)b * 27) * 1024 + (h0 + tyy) * WW + tx;
#pragma unroll
    for (int c27 = 0; c27 < 27; c27++) op[(size_t)c27 << 10] = acc[c27];
}

__global__ void k_offred(const float* __restrict__ b_off) {
    int idx = blockIdx.x * 256 + threadIdx.x;
    if (idx >= 16 * 27 * 1024) return;
    int c27 = (idx >> 10) % 27;
    float v = b_off[c27];
#pragma unroll
    for (int g = 0; g < 4; g++) v += g_off_part[(size_t)g * (16 * 27 * 1024) + idx];
    if (c27 >= 18) v = 1.f / (1.f + expf(-v));
    g_off[idx] = v;
}

// ---------------- combined weight prepack ----------------
__global__ void k_prep(const float* __restrict__ w_dcn, const float* __restrict__ w_up) {
    int idx = blockIdx.x * 256 + threadIdx.x;
    if (idx < 2304 * 128) {
        int o = idx & 127, kc = idx >> 7;
        int k = kc >> 8, c = kc & 255;
        g_wdefT[idx] = w_dcn[((size_t)o * CIN + c) * 9 + k];
    } else {
        int j = idx - 2304 * 128;
        if (j < 4 * 512 * 128) {
            int o = j & 127;
            int kcpar = j >> 7;
            int kc = kcpar & 511, par = kcpar >> 9;
            int i = kc >> 2, dh = (kc >> 1) & 1, dw = kc & 1;
            int py = par >> 1, px = par & 1;
            int kh = 3 - (py + 2 * dh);
            int kw = 3 - (px + 2 * dw);
            g_wupT[j] = w_up[(((size_t)i * 128 + o) * 4 + kh) * 4 + kw];
        }
    }
}

// ---------------- K2: bilinear sampling into samp[b][k][c][p] -----------
__global__ __launch_bounds__(256) void k_sample(const float* __restrict__ x) {
    const int k = blockIdx.x;       // 0..8
    const int b = blockIdx.y;       // 0..15
    const int cgrp = blockIdx.z;    // 0..7 (32 channels each)
    const int t = threadIdx.x;

    __shared__ int   s_idx[4][1024];
    __shared__ float s_w[4][1024];

    const float* offb = g_off + (size_t)b * 27 * 1024;
    const int ky = k / 3 - 1, kx = k % 3 - 1;

    for (int p = t; p < 1024; p += 256) {
        float dy = offb[(size_t)(2 * k) * 1024 + p];
        float dx = offb[(size_t)(2 * k + 1) * 1024 + p];
        float m  = offb[(size_t)(18 + k) * 1024 + p];
        int h = p >> 5, w = p & 31;
        float pyf = (float)(h + ky) + dy;
        float pxf = (float)(w + kx) + dx;
        float y0f = floorf(pyf), x0f = floorf(pxf);
        float wy = pyf - y0f, wx = pxf - x0f;
        int y0 = (int)y0f, x0 = (int)x0f;
#pragma unroll
        for (int slot = 0; slot < 4; slot++) {
            int dyc = slot >> 1, dxc = slot & 1;
            int yc = y0 + dyc, xc = x0 + dxc;
            bool valid = (yc >= 0) && (yc <= HH - 1) && (xc >= 0) && (xc <= WW - 1);
            int yi = min(HH - 1, max(0, yc));
            int xi = min(WW - 1, max(0, xc));
            float wgt = (dyc ? wy : 1.f - wy) * (dxc ? wx : 1.f - wx);
            s_idx[slot][p] = yi * WW + xi;
            s_w[slot][p]   = valid ? wgt * m : 0.f;
        }
    }
    __syncthreads();

    const float* xb = x + ((size_t)b * CIN + cgrp * 32) * 1024;
    float* Sb = g_samp + (((size_t)(b * 9 + k) * CIN) + cgrp * 32) * 1024;

    for (int p = t; p < 1024; p += 256) {
        int   i0 = s_idx[0][p], i1 = s_idx[1][p], i2 = s_idx[2][p], i3 = s_idx[3][p];
        float w0 = s_w[0][p],   w1 = s_w[1][p],   w2 = s_w[2][p],   w3 = s_w[3][p];
        const float* xp = xb;
        float* sp = Sb + p;
#pragma unroll 4
        for (int c = 0; c < 32; c++) {
            float v = w0 * __ldg(xp + i0) + w1 * __ldg(xp + i1) +
                      w2 * __ldg(xp + i2) + w3 * __ldg(xp + i3);
            sp[(size_t)c << 10] = v;
            xp += 1024;
        }
    }
}

// ---------------- K3: deform GEMM, double-buffered, FFMA2 ----------------
__global__ __launch_bounds__(256) void k_gemm_deform(const float* __restrict__ bias) {
    const int pt = blockIdx.x;   // 0..7
    const int b  = blockIdx.y;   // 0..15
    const int bid = blockIdx.y * 8 + blockIdx.x;

    __shared__ float sh[4096];   // 2 x (As 1024 + Bs 1024); Red overlays [0..2047]

    const int t  = threadIdx.x;
    const int tx = t & 15, ty = t >> 4;

    unsigned long long acc2[8][4];
#pragma unroll
    for (int i = 0; i < 8; i++)
#pragma unroll
        for (int j = 0; j < 4; j++) acc2[i][j] = 0ULL;

    const float* Sb = g_samp + (size_t)b * KDEF * 1024 + pt * 128;
    const float4* Ag = reinterpret_cast<const float4*>(g_wdefT);

    const int r  = t >> 5;
    const int c4 = (t & 31) << 2;

    // prologue: tile 0 -> buf 0
    float4 ra = Ag[t];
    float4 rb = *reinterpret_cast<const float4*>(Sb + (size_t)r * 1024 + c4);
    reinterpret_cast<float4*>(sh)[t] = ra;
    *reinterpret_cast<float4*>(sh + 1024 + r * 128 + c4) = rb;
    __syncthreads();

    int buf = 0;
    for (int kc0 = 0; kc0 < KDEF; kc0 += 8) {
        const int nxt = kc0 + 8;
        if (nxt < KDEF) {
            ra = Ag[nxt * 32 + t];
            rb = *reinterpret_cast<const float4*>(Sb + (size_t)(nxt + r) * 1024 + c4);
        }
        const float* As = sh + buf * 2048;
        const float* Bs = As + 1024;
#pragma unroll
        for (int kk = 0; kk < 8; kk++) {
            float a[8];
            *(float4*)&a[0]  = *(const float4*)&As[kk * 128 + ty * 8];
            *(float4*)&a[4]  = *(const float4*)&As[kk * 128 + ty * 8 + 4];
            unsigned long long b2[4];
            *(ulonglong2*)&b2[0] = *(const ulonglong2*)&Bs[kk * 128 + tx * 8];
            *(ulonglong2*)&b2[2] = *(const ulonglong2*)&Bs[kk * 128 + tx * 8 + 4];
            unsigned long long a2[8];
#pragma unroll
            for (int i = 0; i < 8; i++) a2[i] = pack2_dup(a[i]);
#pragma unroll
            for (int i = 0; i < 8; i++)
#pragma unroll
                for (int jp = 0; jp < 4; jp++)
                    ffma2(acc2[i][jp], a2[i], b2[jp]);
        }
        if (nxt < KDEF) {
            float* d = sh + (buf ^ 1) * 2048;
            reinterpret_cast<float4*>(d)[t] = ra;
            *reinterpret_cast<float4*>(d + 1024 + r * 128 + c4) = rb;
        }
        __syncthreads();
        buf ^= 1;
    }

    // unpack
    float acc[8][8];
#pragma unroll
    for (int i = 0; i < 8; i++)
#pragma unroll
        for (int jp = 0; jp < 4; jp++)
            unpack2(acc2[i][jp], acc[i][2 * jp], acc[i][2 * jp + 1]);

    // epilogue: bias, write, BN1 partials (Red overlays sh[0..2047])
    float* Red = sh;
    float* Y = g_y + ((size_t)b * COUT) * 1024 + pt * 128;
    float rs[8], rq[8];
#pragma unroll
    for (int i = 0; i < 8; i++) {
        int o = ty * 8 + i;
        float bi = __ldg(bias + o);
        float s = 0.f, q = 0.f;
#pragma unroll
        for (int j = 0; j < 8; j++) {
            float v = acc[i][j] + bi;
            acc[i][j] = v;
            s += v; q += v * v;
        }
        rs[i] = s; rq[i] = q;
        *(float4*)(Y + (size_t)o * 1024 + tx * 8)     = *(float4*)&acc[i][0];
        *(float4*)(Y + (size_t)o * 1024 + tx * 8 + 4) = *(float4*)&acc[i][4];
    }
#pragma unroll
    for (int i = 0; i < 8; i++) Red[tx * 128 + ty * 8 + i] = rs[i];
    __syncthreads();
    if (t < 128) {
        float s = 0.f;
#pragma unroll
        for (int xq = 0; xq < 16; xq++) s += Red[xq * 128 + t];
        g_part1[((size_t)bid * 128 + t) * 2 + 0] = s;
    }
    __syncthreads();
#pragma unroll
    for (int i = 0; i < 8; i++) Red[tx * 128 + ty * 8 + i] = rq[i];
    __syncthreads();
    if (t < 128) {
        float q = 0.f;
#pragma unroll
        for (int xq = 0; xq < 16; xq++) q += Red[xq * 128 + t];
        g_part1[((size_t)bid * 128 + t) * 2 + 1] = q;
    }
}

// ---------------- BN1 finalize ----------------
__global__ void k_bn1(const float* __restrict__ g1, const float* __restrict__ bt1) {
    int o = threadIdx.x;
    float s = 0.f, q = 0.f;
    for (int blk = 0; blk < 128; blk++) {
        s += g_part1[((size_t)blk * 128 + o) * 2 + 0];
        q += g_part1[((size_t)blk * 128 + o) * 2 + 1];
    }
    float mean = s / (float)N1TOT;
    float var  = q / (float)N1TOT - mean * mean;
    float sc = g1[o] * rsqrtf(var + 1e-5f);
    g_scale1[o] = sc;
    g_shift1[o] = bt1[o] - mean * sc;
}

// ---------------- K6: deconv (4 parity 2x2 convs), BN1 fused, FFMA2 ------
__global__ __launch_bounds__(256) void k_deconv() {
    const int pt  = blockIdx.x;   // 0..7
    const int par = blockIdx.y;   // 0..3
    const int b   = blockIdx.z;   // 0..15
    const int py = par >> 1, px = par & 1;
    const int a0 = pt * 4;
    const int bid = (blockIdx.z * 4 + blockIdx.y) * 8 + blockIdx.x;

    __shared__ float sh[4096];

    const int t  = threadIdx.x;
    const int tx = t & 15, ty = t >> 4;

    unsigned long long acc2[8][4];
#pragma unroll
    for (int i = 0; i < 8; i++)
#pragma unroll
        for (int j = 0; j < 4; j++) acc2[i][j] = 0ULL;

    const float4* Ag = reinterpret_cast<const float4*>(g_wupT + (size_t)par * KUP * 128);
    const float* Yb = g_y + (size_t)b * COUT * 1024;

    const int kkld = t >> 5;
    const int n0   = (t & 31) << 2;

    auto loadB = [&](int kc0, float* rv) {
        int kc = kc0 + kkld;
        int i  = kc >> 2, dh = (kc >> 1) & 1, dw = kc & 1;
        const float* Yp = Yb + (size_t)i * 1024;
        float sc = g_scale1[i], shv = g_shift1[i];
#pragma unroll
        for (int jj = 0; jj < 4; jj++) {
            int n = n0 + jj;
            int arow = n >> 5, c = n & 31;
            int iy = a0 + arow + py + dh - 1;
            int ix = c + px + dw - 1;
            float v = 0.f;
            if (iy >= 0 && iy < HH && ix >= 0 && ix < WW)
                v = fmaxf(0.f, fmaf(__ldg(Yp + iy * WW + ix), sc, shv));
            rv[jj] = v;
        }
    };

    // prologue
    float4 ra = Ag[t];
    float rv[4];
    loadB(0, rv);
    reinterpret_cast<float4*>(sh)[t] = ra;
    *reinterpret_cast<float4*>(sh + 1024 + kkld * 128 + n0) = *(float4*)rv;
    __syncthreads();

    int buf = 0;
    for (int kc0 = 0; kc0 < KUP; kc0 += 8) {
        const int nxt = kc0 + 8;
        if (nxt < KUP) {
            ra = Ag[nxt * 32 + t];
            loadB(nxt, rv);
        }
        const float* As = sh + buf * 2048;
        const float* Bs = As + 1024;
#pragma unroll
        for (int kk = 0; kk < 8; kk++) {
            float a[8];
            *(float4*)&a[0]  = *(const float4*)&As[kk * 128 + ty * 8];
            *(float4*)&a[4]  = *(const float4*)&As[kk * 128 + ty * 8 + 4];
            unsigned long long b2[4];
            *(ulonglong2*)&b2[0] = *(const ulonglong2*)&Bs[kk * 128 + tx * 8];
            *(ulonglong2*)&b2[2] = *(const ulonglong2*)&Bs[kk * 128 + tx * 8 + 4];
            unsigned long long a2[8];
#pragma unroll
            for (int i = 0; i < 8; i++) a2[i] = pack2_dup(a[i]);
#pragma unroll
            for (int i = 0; i < 8; i++)
#pragma unroll
                for (int jp = 0; jp < 4; jp++)
                    ffma2(acc2[i][jp], a2[i], b2[jp]);
        }
        if (nxt < KUP) {
            float* d = sh + (buf ^ 1) * 2048;
            reinterpret_cast<float4*>(d)[t] = ra;
            *reinterpret_cast<float4*>(d + 1024 + kkld * 128 + n0) = *(float4*)rv;
        }
        __syncthreads();
        buf ^= 1;
    }

    float acc[8][8];
#pragma unroll
    for (int i = 0; i < 8; i++)
#pragma unroll
        for (int jp = 0; jp < 4; jp++)
            unpack2(acc2[i][jp], acc[i][2 * jp], acc[i][2 * jp + 1]);

    float* Red = sh;
    float* Z = g_z + ((size_t)(b * 4 + par) * COUT) * 1024 + pt * 128;
    float rs[8], rq[8];
#pragma unroll
    for (int i = 0; i < 8; i++) {
        int o = ty * 8 + i;
        float s = 0.f, q = 0.f;
#pragma unroll
        for (int j = 0; j < 8; j++) { float v = acc[i][j]; s += v; q += v * v; }
        rs[i] = s; rq[i] = q;
        *(float4*)(Z + (size_t)o * 1024 + tx * 8)     = *(float4*)&acc[i][0];
        *(float4*)(Z + (size_t)o * 1024 + tx * 8 + 4) = *(float4*)&acc[i][4];
    }
#pragma unroll
    for (int i = 0; i < 8; i++) Red[tx * 128 + ty * 8 + i] = rs[i];
    __syncthreads();
    if (t < 128) {
        float s = 0.f;
#pragma unroll
        for (int xq = 0; xq < 16; xq++) s += Red[xq * 128 + t];
        g_part2[((size_t)bid * 128 + t) * 2 + 0] = s;
    }
    __syncthreads();
#pragma unroll
    for (int i = 0; i < 8; i++) Red[tx * 128 + ty * 8 + i] = rq[i];
    __syncthreads();
    if (t < 128) {
        float q = 0.f;
#pragma unroll
        for (int xq = 0; xq < 16; xq++) q += Red[xq * 128 + t];
        g_part2[((size_t)bid * 128 + t) * 2 + 1] = q;
    }
}

// ---------------- BN2 finalize + final output ----------------
__global__ void k_bn2(const float* __restrict__ g2, const float* __restrict__ bt2) {
    int o = threadIdx.x;
    float s = 0.f, q = 0.f;
    for (int blk = 0; blk < 512; blk++) {
        s += g_part2[((size_t)blk * 128 + o) * 2 + 0];
        q += g_part2[((size_t)blk * 128 + o) * 2 + 1];
    }
    float mean = s / (float)N2TOT;
    float var  = q / (float)N2TOT - mean * mean;
    float sc = g2[o] * rsqrtf(var + 1e-5f);
    g_scale2[o] = sc;
    g_shift2[o] = bt2[o] - mean * sc;
}

__global__ void k_out(float* __restrict__ out) {
    int f = blockIdx.x * 256 + threadIdx.x;
    int e = f << 2;
    int b   = e >> 19;
    int o   = (e >> 12) & 127;
    int oy  = (e >> 6) & 63;
    int ox0 = e & 63;
    float sc = g_scale2[o], shv = g_shift2[o];
    int a = oy >> 1;
    int pybit = oy & 1;
    float r[4];
#pragma unroll
    for (int j = 0; j < 4; j++) {
        int ox = ox0 + j;
        int par = pybit * 2 + (ox & 1);
        int c = ox >> 1;
        float z = g_z[((size_t)(b * 4 + par) * COUT + o) * 1024 + a * 32 + c];
        r[j] = fmaxf(0.f, z * sc + shv);
    }
    reinterpret_cast<float4*>(out)[f] = *(float4*)r;
}

// ---------------- launcher ----------------
extern "C" void kernel_launch(void* const* d_in, const int* in_sizes, int n_in,
                              void* d_out, int out_size) {
    const float* x     = (const float*)d_in[0];
    const float* w_off = (const float*)d_in[1];
    const float* b_off = (const float*)d_in[2];
    const float* w_dcn = (const float*)d_in[3];
    const float* b_dcn = (const float*)d_in[4];
    const float* g1    = (const float*)d_in[5];
    const float* bt1   = (const float*)d_in[6];
    const float* w_up  = (const float*)d_in[7];
    const float* g2    = (const float*)d_in[8];
    const float* bt2   = (const float*)d_in[9];
    float* out = (float*)d_out;

    k_offconv<<<dim3(4, 16, 4), 256>>>(x, w_off);
    k_offred<<<1728, 256>>>(b_off);
    k_prep<<<2176, 256>>>(w_dcn, w_up);

    k_sample<<<dim3(9, 16, 8), 256>>>(x);

    k_gemm_deform<<<dim3(8, 16), 256>>>(b_dcn);
    k_bn1<<<1, 128>>>(g1, bt1);

    k_deconv<<<dim3(8, 4, 16), 256>>>();
    k_bn2<<<1, 128>>>(g2, bt2);

    k_out<<<8192, 256>>>(out);
}